// round 2
// baseline (speedup 1.0000x reference)
#include <cuda_runtime.h>
#include <math.h>

// ---------------- problem constants ----------------
#define BATCH 32
#define CCH   768
#define TMAX  1022
#define DDIM  64
#define MEMB  512
#define TP    511
#define NVEC  (BATCH * TP)        // 16352
#define NPART (NVEC / 8)          // 2044 (VQ blocks: 8 warps/block, 1 vec/warp)

// ---------------- device scratch (static, no runtime alloc) ----------------
__device__ float g_bufA[(size_t)BATCH * CCH * TMAX];   // ~100.5 MB
__device__ float g_bufB[(size_t)BATCH * CCH * TMAX];   // ~100.5 MB
__device__ float g_z[(size_t)NVEC * DDIM];             // [B*Tp, 64]
__device__ float g_Et[DDIM * MEMB];                    // embedding transposed [64][512]
__device__ float g_esq[MEMB];                          // ||e||^2
__device__ int   g_counts[MEMB];
__device__ float g_partial[NPART];

// ============================================================
// Implicit-GEMM conv1d + BN + ReLU.
//   Y[b, co, t] = relu( BN( sum_{ci,k} W[co,ci,k] * X[b,ci,t*S + k - P] ) )
// GEMM view: M = 768 (co), N = Tout (per batch), Kdim = Cin*K.
// Tile 128x128x8, 256 threads, 8x8 accum per thread.
// ============================================================
template<int K, int STRIDE, int PAD>
__global__ __launch_bounds__(256) void conv_bn_relu(
    const float* __restrict__ X, const float* __restrict__ W,
    const float* __restrict__ gamma, const float* __restrict__ beta,
    const float* __restrict__ mean,  const float* __restrict__ var,
    float* __restrict__ Y, int Cin, int Tin, int Tout)
{
    const int Kdim = Cin * K;            // multiple of 8 for all layers
    __shared__ float As[8][128];         // W tile, transposed: As[p][m]
    __shared__ float Bs[8][128];         // X tile: Bs[p][n]

    const int tid = threadIdx.x;
    const int b   = blockIdx.z;
    const int m0  = blockIdx.y * 128;    // co tile
    const int t0  = blockIdx.x * 128;    // t tile

    const float* Xb = X + (size_t)b * Cin * Tin;

    float acc[8][8];
    #pragma unroll
    for (int i = 0; i < 8; i++)
        #pragma unroll
        for (int j = 0; j < 8; j++) acc[i][j] = 0.f;

    const int a_row = tid >> 1;          // 0..127 (m)
    const int a_col = (tid & 1) * 4;     // 0 or 4 (p)
    const int b_p   = tid >> 5;          // 0..7   (p)
    const int b_n0  = (tid & 31) * 4;    // n base

    const int tx = tid & 15;             // n micro-tile
    const int ty = tid >> 4;             // m micro-tile

    for (int p0 = 0; p0 < Kdim; p0 += 8) {
        // --- load W tile (float4, Kdim % 8 == 0 so aligned) ---
        float4 wv = *reinterpret_cast<const float4*>(
            W + (size_t)(m0 + a_row) * Kdim + p0 + a_col);
        As[a_col + 0][a_row] = wv.x;
        As[a_col + 1][a_row] = wv.y;
        As[a_col + 2][a_row] = wv.z;
        As[a_col + 3][a_row] = wv.w;

        // --- load X tile with implicit im2col + bounds (padding) ---
        {
            const int p  = p0 + b_p;
            const int ci = p / K;
            const int k  = p - ci * K;
            const float* Xrow = Xb + (size_t)ci * Tin;
            #pragma unroll
            for (int j = 0; j < 4; j++) {
                const int n   = b_n0 + j;
                const int tin = (t0 + n) * STRIDE + k - PAD;
                float v = 0.f;
                if (tin >= 0 && tin < Tin) v = Xrow[tin];
                Bs[b_p][n] = v;
            }
        }
        __syncthreads();

        #pragma unroll
        for (int kk = 0; kk < 8; kk++) {
            float4 a0 = *reinterpret_cast<const float4*>(&As[kk][ty * 8]);
            float4 a1 = *reinterpret_cast<const float4*>(&As[kk][ty * 8 + 4]);
            float4 c0 = *reinterpret_cast<const float4*>(&Bs[kk][tx * 8]);
            float4 c1 = *reinterpret_cast<const float4*>(&Bs[kk][tx * 8 + 4]);
            float ar[8] = {a0.x, a0.y, a0.z, a0.w, a1.x, a1.y, a1.z, a1.w};
            float br[8] = {c0.x, c0.y, c0.z, c0.w, c1.x, c1.y, c1.z, c1.w};
            #pragma unroll
            for (int i = 0; i < 8; i++)
                #pragma unroll
                for (int j = 0; j < 8; j++)
                    acc[i][j] = fmaf(ar[i], br[j], acc[i][j]);
        }
        __syncthreads();
    }

    // --- fused BN + ReLU epilogue ---
    #pragma unroll
    for (int i = 0; i < 8; i++) {
        const int co = m0 + ty * 8 + i;                 // M = 768 = 6*128 exact
        const float inv = gamma[co] * rsqrtf(var[co] + 1e-5f);
        const float sh  = beta[co] - mean[co] * inv;
        float* Yrow = Y + ((size_t)b * CCH + co) * Tout;
        #pragma unroll
        for (int j = 0; j < 8; j++) {
            const int t = t0 + tx * 8 + j;
            if (t < Tout) {
                float v = fmaf(acc[i][j], inv, sh);
                Yrow[t] = v > 0.f ? v : 0.f;
            }
        }
    }
}

// ============================================================
// conv6 (1x1, 768->64) + bias, fused transpose: Z[b*Tp + t][d]
// One block: 64 t x 64 d for one batch. 256 threads, 4x4 per thread.
// ============================================================
__global__ __launch_bounds__(256) void conv6_kernel(
    const float* __restrict__ X, const float* __restrict__ W6,
    const float* __restrict__ b6, float* __restrict__ Z)
{
    __shared__ float Xs[64][65];   // [ci][t]
    __shared__ float Ws[64][65];   // [d][ci]
    const int tid = threadIdx.x;
    const int b   = blockIdx.y;
    const int t0  = blockIdx.x * 64;

    const int tdx = tid & 15;      // d group
    const int ttx = tid >> 4;      // t group

    float acc[4][4];
    #pragma unroll
    for (int i = 0; i < 4; i++)
        #pragma unroll
        for (int j = 0; j < 4; j++) acc[i][j] = 0.f;

    const int lt = tid & 63;
    const int lr = tid >> 6;       // 0..3

    for (int c0 = 0; c0 < CCH; c0 += 64) {
        #pragma unroll
        for (int r = 0; r < 16; r++) {
            const int ci = lr + r * 4;
            const int t  = t0 + lt;
            Xs[ci][lt] = (t < TP) ? X[((size_t)b * CCH + c0 + ci) * TP + t] : 0.f;
            const int d  = lr + r * 4;
            Ws[d][lt] = W6[(size_t)d * CCH + c0 + lt];
        }
        __syncthreads();

        #pragma unroll 8
        for (int ci = 0; ci < 64; ci++) {
            float w[4], x[4];
            #pragma unroll
            for (int i = 0; i < 4; i++) w[i] = Ws[tdx * 4 + i][ci];
            #pragma unroll
            for (int j = 0; j < 4; j++) x[j] = Xs[ci][ttx * 4 + j];
            #pragma unroll
            for (int i = 0; i < 4; i++)
                #pragma unroll
                for (int j = 0; j < 4; j++)
                    acc[i][j] = fmaf(w[i], x[j], acc[i][j]);
        }
        __syncthreads();
    }

    #pragma unroll
    for (int i = 0; i < 4; i++) {
        const int d = tdx * 4 + i;
        const float bias = b6[d];
        #pragma unroll
        for (int j = 0; j < 4; j++) {
            const int t = t0 + ttx * 4 + j;
            if (t < TP)
                Z[((size_t)(b * TP + t)) * DDIM + d] = acc[i][j] + bias;
        }
    }
}

// ============================================================
// VQ prep: transpose embedding, compute ||e||^2, zero counts.
// ============================================================
__global__ void prep_vq(const float* __restrict__ E)
{
    const int e = threadIdx.x;     // 512 threads
    float s = 0.f;
    #pragma unroll
    for (int d = 0; d < DDIM; d++) {
        const float v = E[(size_t)e * DDIM + d];
        s = fmaf(v, v, s);
        g_Et[d * MEMB + e] = v;
    }
    g_esq[e] = s;
    g_counts[e] = 0;
}

// ============================================================
// VQ: one warp per vector. argmin_e ( ||e||^2 - 2 x.e ), first-min ties.
// Writes q_st = z + (E[idx]-z), per-block loss partial, counts histogram.
// ============================================================
__global__ __launch_bounds__(256) void vq_kernel(
    const float* __restrict__ Z, const float* __restrict__ E,
    float* __restrict__ out)
{
    __shared__ float zsh[8][64];
    __shared__ float pw[8];
    const int tid  = threadIdx.x;
    const int w    = tid >> 5;
    const int lane = tid & 31;
    const int vec  = blockIdx.x * 8 + w;   // always < NVEC (2044*8 exact)

    zsh[w][lane]      = Z[(size_t)vec * 64 + lane];
    zsh[w][lane + 32] = Z[(size_t)vec * 64 + lane + 32];
    __syncwarp();

    float best = 3.4e38f;
    int   bidx = 0;
    #pragma unroll
    for (int i = 0; i < 16; i++) {
        const int e = lane + 32 * i;
        float dot = 0.f;
        #pragma unroll
        for (int d = 0; d < 64; d++)
            dot = fmaf(zsh[w][d], g_Et[d * MEMB + e], dot);
        const float dist = g_esq[e] - 2.f * dot;
        if (dist < best) { best = dist; bidx = e; }   // strict < keeps lowest e
    }
    #pragma unroll
    for (int off = 16; off > 0; off >>= 1) {
        const float ob = __shfl_down_sync(0xFFFFFFFFu, best, off);
        const int   oi = __shfl_down_sync(0xFFFFFFFFu, bidx, off);
        if (ob < best || (ob == best && oi < bidx)) { best = ob; bidx = oi; }
    }
    bidx = __shfl_sync(0xFFFFFFFFu, bidx, 0);

    float lsum = 0.f;
    #pragma unroll
    for (int h = 0; h < 2; h++) {
        const int d  = lane + 32 * h;
        const float zv = zsh[w][d];
        const float q  = E[(size_t)bidx * 64 + d];
        out[(size_t)vec * 64 + d] = zv + (q - zv);    // straight-through
        const float diff = zv - q;
        lsum = fmaf(diff, diff, lsum);
    }
    #pragma unroll
    for (int off = 16; off > 0; off >>= 1)
        lsum += __shfl_down_sync(0xFFFFFFFFu, lsum, off);

    if (lane == 0) {
        pw[w] = lsum;
        atomicAdd(&g_counts[bidx], 1);
    }
    __syncthreads();
    if (tid == 0) {
        float s = 0.f;
        #pragma unroll
        for (int i = 0; i < 8; i++) s += pw[i];
        g_partial[blockIdx.x] = s;
    }
}

// ============================================================
// Finalize: loss = 0.25 * mean((z-q)^2); perplexity from counts.
// ============================================================
__global__ __launch_bounds__(1024) void finalize_kernel(float* __restrict__ out)
{
    __shared__ float sh[1024];
    const int tid = threadIdx.x;

    float s = 0.f;
    for (int i = tid; i < NPART; i += 1024) s += g_partial[i];
    sh[tid] = s; __syncthreads();
    for (int off = 512; off > 0; off >>= 1) {
        if (tid < off) sh[tid] += sh[tid + off];
        __syncthreads();
    }
    const float total = sh[0];
    __syncthreads();

    float h = 0.f;
    if (tid < MEMB) {
        const float p = (float)g_counts[tid] / (float)NVEC;
        h = p * logf(p + 1e-10f);
    }
    sh[tid] = h; __syncthreads();
    for (int off = 512; off > 0; off >>= 1) {
        if (tid < off) sh[tid] += sh[tid + off];
        __syncthreads();
    }
    if (tid == 0) {
        out[(size_t)NVEC * DDIM]     = 0.25f * total / (float)((size_t)NVEC * DDIM);
        out[(size_t)NVEC * DDIM + 1] = expf(-sh[0]);
    }
}

// ============================================================
// launch
// ============================================================
extern "C" void kernel_launch(void* const* d_in, const int* in_sizes, int n_in,
                              void* d_out, int out_size)
{
    const float* mels  = (const float*)d_in[0];
    const float* w1    = (const float*)d_in[1];
    const float* w2    = (const float*)d_in[2];
    const float* w3    = (const float*)d_in[3];
    const float* w4    = (const float*)d_in[4];
    const float* w5    = (const float*)d_in[5];
    const float* w6    = (const float*)d_in[6];
    const float* b6    = (const float*)d_in[7];
    const float* gamma = (const float*)d_in[8];
    const float* beta  = (const float*)d_in[9];
    const float* mean  = (const float*)d_in[10];
    const float* var   = (const float*)d_in[11];
    const float* emb   = (const float*)d_in[12];
    float* out = (float*)d_out;

    float *bufA, *bufB, *zbuf;
    cudaGetSymbolAddress((void**)&bufA, g_bufA);
    cudaGetSymbolAddress((void**)&bufB, g_bufB);
    cudaGetSymbolAddress((void**)&zbuf, g_z);

    const dim3 blk(256);
    // conv1: [32,80,1024] -> [32,768,1022], K3 s1 p0, BN0
    conv_bn_relu<3,1,0><<<dim3(8, 6, BATCH), blk>>>(
        mels, w1, gamma, beta, mean, var, bufA, 80, 1024, 1022);
    // conv2: K3 s1 p1, BN1
    conv_bn_relu<3,1,1><<<dim3(8, 6, BATCH), blk>>>(
        bufA, w2, gamma + CCH, beta + CCH, mean + CCH, var + CCH,
        bufB, CCH, 1022, 1022);
    // conv3: K4 s2 p1 -> T=511, BN2
    conv_bn_relu<4,2,1><<<dim3(4, 6, BATCH), blk>>>(
        bufB, w3, gamma + 2*CCH, beta + 2*CCH, mean + 2*CCH, var + 2*CCH,
        bufA, CCH, 1022, 511);
    // conv4: K3 s1 p1, BN3
    conv_bn_relu<3,1,1><<<dim3(4, 6, BATCH), blk>>>(
        bufA, w4, gamma + 3*CCH, beta + 3*CCH, mean + 3*CCH, var + 3*CCH,
        bufB, CCH, 511, 511);
    // conv5: K3 s1 p1, BN4
    conv_bn_relu<3,1,1><<<dim3(4, 6, BATCH), blk>>>(
        bufB, w5, gamma + 4*CCH, beta + 4*CCH, mean + 4*CCH, var + 4*CCH,
        bufA, CCH, 511, 511);
    // conv6 1x1 + bias + transpose -> z [B*Tp, 64]
    conv6_kernel<<<dim3(8, BATCH), blk>>>(bufA, w6, b6, zbuf);
    // VQ
    prep_vq<<<1, MEMB>>>(emb);
    vq_kernel<<<NPART, blk>>>(zbuf, emb, out);
    finalize_kernel<<<1, 1024>>>(out);
}

// round 4
// speedup vs baseline: 2.7214x; 2.7214x over previous
#include <cuda_runtime.h>
#include <cuda_fp16.h>
#include <math.h>
#include <stdint.h>

// ---------------- problem constants ----------------
#define BATCH 32
#define CCH   768
#define DDIM  64
#define MEMB  512
#define TP    511
#define NVEC  (BATCH * TP)
#define NPART (NVEC / 8)

// ---------------- device scratch (static) ----------------
__device__ __half g_XAh[(size_t)BATCH * 1022 * CCH];
__device__ __half g_XAl[(size_t)BATCH * 1022 * CCH];
__device__ __half g_XBh[(size_t)BATCH * 1022 * CCH];
__device__ __half g_XBl[(size_t)BATCH * 1022 * CCH];
__device__ __half g_M1h[(size_t)BATCH * 1024 * 128];
__device__ __half g_M1l[(size_t)BATCH * 1024 * 128];
__device__ __half g_W1h[768 * 3 * 128], g_W1l[768 * 3 * 128];
__device__ __half g_W2h[768 * 3 * 768], g_W2l[768 * 3 * 768];
__device__ __half g_W3h[768 * 4 * 768], g_W3l[768 * 4 * 768];
__device__ __half g_W4h[768 * 3 * 768], g_W4l[768 * 3 * 768];
__device__ __half g_W5h[768 * 3 * 768], g_W5l[768 * 3 * 768];
__device__ float g_C5[(size_t)BATCH * TP * CCH];     // [b][t][c] fp32
__device__ float g_z[(size_t)NVEC * DDIM];
__device__ float g_Et[DDIM * MEMB];
__device__ float g_esq[MEMB];
__device__ int   g_counts[MEMB];
__device__ float g_partial[NPART];

// ---------------- helpers ----------------
__device__ __forceinline__ uint32_t smem_u32(const void* p) {
    uint32_t a;
    asm("{ .reg .u64 t; cvta.to.shared.u64 t, %1; cvt.u32.u64 %0, t; }"
        : "=r"(a) : "l"(p));
    return a;
}

#define LDMX4(r0, r1, r2, r3, addr) \
    asm volatile("ldmatrix.sync.aligned.m8n8.x4.shared.b16 {%0,%1,%2,%3}, [%4];" \
        : "=r"(r0), "=r"(r1), "=r"(r2), "=r"(r3) : "r"(addr))

__device__ __forceinline__ void mma16816(float* d, const uint32_t* a, const uint32_t* b) {
    asm volatile(
        "mma.sync.aligned.m16n8k16.row.col.f32.f16.f16.f32 "
        "{%0,%1,%2,%3}, {%4,%5,%6,%7}, {%8,%9}, {%0,%1,%2,%3};"
        : "+f"(d[0]), "+f"(d[1]), "+f"(d[2]), "+f"(d[3])
        : "r"(a[0]), "r"(a[1]), "r"(a[2]), "r"(a[3]), "r"(b[0]), "r"(b[1]));
}

// smem: double buffer, each buf = A(20480) + B(20480). total 81920.
#define ABUF   20480
#define BUFSZ  40960
#define SM_TOT 81920
#define RSTR   80        // bytes per 32-half row (64B data + 16B pad)

// ============================================================
// Implicit-GEMM conv1d + BN + ReLU via mma.sync fp16 3-term split.
// BM=128 (co) x BN=128 (t), BK=32. 256 thr, warp tile 64x32.
// X planes [b][t][Cin] hi/lo fp16; W planes [co][tap*Cin+ci] hi/lo.
// ============================================================
template<int KTAP, int S, int P, bool SPLITOUT>
__global__ void __launch_bounds__(256) conv_mma(
    const __half* __restrict__ Xh, const __half* __restrict__ Xl,
    const __half* __restrict__ Wh, const __half* __restrict__ Wl,
    const float* __restrict__ gam, const float* __restrict__ bet,
    const float* __restrict__ mu,  const float* __restrict__ var,
    __half* __restrict__ Yh, __half* __restrict__ Yl, float* __restrict__ Yf,
    int Cin, int Tin, int Tout)
{
    extern __shared__ char smem[];
    const uint32_t sb = smem_u32(smem);
    const int tid = threadIdx.x;
    const int lane = tid & 31, w = tid >> 5;
    const int mw = w & 1, nw = w >> 1;          // warp: 2(m) x 4(n)
    const int b = blockIdx.z, m0 = blockIdx.y * 128, t0 = blockIdx.x * 128;
    const int Kp = KTAP * Cin;
    const int cich = Cin >> 5;
    const int nchunk = Kp >> 5;

    // loader decode (4 iters x 256 thr = 1024 16B segs: 2 planes x 128 rows x 4 segs)
    // idx = i*256+tid: plane=idx>>9, r=(idx>>2)&127, seg=idx&3
    float acc[4][4][4];
    #pragma unroll
    for (int i = 0; i < 4; i++)
        #pragma unroll
        for (int j = 0; j < 4; j++)
            #pragma unroll
            for (int r = 0; r < 4; r++) acc[i][j][r] = 0.f;

    uint4 Ar[4], Br[4];

    auto ldg = [&](int kc) {
        const int tap = kc / cich;
        const int ci0 = (kc - tap * cich) << 5;
        #pragma unroll
        for (int i = 0; i < 4; i++) {
            const int idx = i * 256 + tid;
            const int pl = idx >> 9, r = (idx >> 2) & 127, seg = idx & 3;
            const __half* W = pl ? Wl : Wh;
            Ar[i] = *(const uint4*)(W + (size_t)(m0 + r) * Kp + kc * 32 + seg * 8);
            const int t_in = (t0 + r) * S + tap - P;
            uint4 v = make_uint4(0u, 0u, 0u, 0u);
            if (t_in >= 0 && t_in < Tin) {
                const __half* X = pl ? Xl : Xh;
                v = *(const uint4*)(X + ((size_t)b * Tin + t_in) * Cin + ci0 + seg * 8);
            }
            Br[i] = v;
        }
    };
    auto sts = [&](int buf) {
        char* base = smem + buf * BUFSZ;
        #pragma unroll
        for (int i = 0; i < 4; i++) {
            const int idx = i * 256 + tid;
            const int pl = idx >> 9, r = (idx >> 2) & 127, seg = idx & 3;
            *(uint4*)(base + pl * 10240 + r * RSTR + seg * 16) = Ar[i];
            *(uint4*)(base + ABUF + pl * 10240 + r * RSTR + seg * 16) = Br[i];
        }
    };
    // NOTE: planes within A buf are 128 rows apart? No: 128 rows * 80B = 10240 per plane. OK.

    // per-thread ldmatrix base offsets (within one plane)
    const uint32_t aoff = (uint32_t)((mw * 64 + (lane & 15)) * RSTR + (lane >> 4) * 16);
    const uint32_t boff = (uint32_t)((nw * 32 + (lane & 7) + ((lane >> 4) << 3)) * RSTR
                                     + ((lane >> 3) & 1) * 16);

    ldg(0);
    sts(0);
    __syncthreads();

    for (int kc = 0; kc < nchunk; kc++) {
        const int cur = kc & 1;
        if (kc + 1 < nchunk) ldg(kc + 1);

        const uint32_t sa = sb + cur * BUFSZ;
        const uint32_t sbB = sa + ABUF;
        #pragma unroll
        for (int ks = 0; ks < 2; ks++) {
            uint32_t af[2][4][4], bf[2][4][2];
            #pragma unroll
            for (int pl = 0; pl < 2; pl++) {
                const uint32_t pa = sa + pl * 10240 + aoff + ks * 32;
                #pragma unroll
                for (int mt = 0; mt < 4; mt++)
                    LDMX4(af[pl][mt][0], af[pl][mt][1], af[pl][mt][2], af[pl][mt][3],
                          pa + mt * (16 * RSTR));
                const uint32_t pb = sbB + pl * 10240 + boff + ks * 32;
                #pragma unroll
                for (int nc = 0; nc < 2; nc++)
                    LDMX4(bf[pl][2 * nc][0], bf[pl][2 * nc][1],
                          bf[pl][2 * nc + 1][0], bf[pl][2 * nc + 1][1],
                          pb + nc * (16 * RSTR));
            }
            #pragma unroll
            for (int mt = 0; mt < 4; mt++)
                #pragma unroll
                for (int nt = 0; nt < 4; nt++) {
                    mma16816(acc[mt][nt], af[0][mt], bf[0][nt]);   // hi*hi
                    mma16816(acc[mt][nt], af[0][mt], bf[1][nt]);   // hi*lo
                    mma16816(acc[mt][nt], af[1][mt], bf[0][nt]);   // lo*hi
                }
        }
        if (kc + 1 < nchunk) sts((kc + 1) & 1);
        __syncthreads();
    }

    // ---------- epilogue: stage [n][m] in smem, BN+ReLU, coalesced stores ----------
    float* eps = (float*)(smem + w * 9216);   // 32 rows x 72 floats
    #pragma unroll
    for (int mt = 0; mt < 4; mt++)
        #pragma unroll
        for (int nt = 0; nt < 4; nt++)
            #pragma unroll
            for (int r = 0; r < 4; r++) {
                const int nl = nt * 8 + 2 * (lane & 3) + (r & 1);
                const int ml = mt * 16 + (lane >> 2) + ((r >> 1) << 3);
                eps[nl * 72 + ml] = acc[mt][nt][r];
            }
    __syncwarp();

    const int cg = m0 + mw * 64 + lane * 2;
    const float inv0 = gam[cg] * rsqrtf(var[cg] + 1e-5f);
    const float sh0  = bet[cg] - mu[cg] * inv0;
    const float inv1 = gam[cg + 1] * rsqrtf(var[cg + 1] + 1e-5f);
    const float sh1  = bet[cg + 1] - mu[cg + 1] * inv1;

    #pragma unroll 4
    for (int rn = 0; rn < 32; rn++) {
        const int t = t0 + nw * 32 + rn;
        if (t < Tout) {
            float v0 = fmaf(eps[rn * 72 + lane * 2], inv0, sh0);
            float v1 = fmaf(eps[rn * 72 + lane * 2 + 1], inv1, sh1);
            v0 = v0 > 0.f ? v0 : 0.f;
            v1 = v1 > 0.f ? v1 : 0.f;
            const size_t o = ((size_t)b * Tout + t) * CCH + cg;
            if (SPLITOUT) {
                const __half h0 = __float2half_rn(v0);
                const __half h1 = __float2half_rn(v1);
                const __half l0 = __float2half_rn(v0 - __half2float(h0));
                const __half l1 = __float2half_rn(v1 - __half2float(h1));
                *(__half2*)(Yh + o) = __halves2half2(h0, h1);
                *(__half2*)(Yl + o) = __halves2half2(l0, l1);
            } else {
                *(float2*)(Yf + o) = make_float2(v0, v1);
            }
        }
    }
}

// ============================================================
// Prep: reorder weights [co][ci][k] -> [co][tap*Cpad+ci], split hi/lo fp16.
// ============================================================
__global__ void prep_w(const float* __restrict__ src, __half* __restrict__ dh,
                       __half* __restrict__ dl, int Cin, int Cpad, int K)
{
    const int idx = blockIdx.x * 256 + threadIdx.x;
    if (idx >= 768 * K * Cpad) return;
    const int ci = idx % Cpad;
    const int r  = idx / Cpad;
    const int k  = r % K, co = r / K;
    const float v = (ci < Cin) ? src[((size_t)co * Cin + ci) * K + k] : 0.f;
    const __half h = __float2half_rn(v);
    dh[idx] = h;
    dl[idx] = __float2half_rn(v - __half2float(h));
}

// ============================================================
// Prep: transpose mels [b][80][1024] -> [b][1024][128] halves hi/lo (pad ch).
// ============================================================
__global__ void prep_mels(const float* __restrict__ mels)
{
    __shared__ float ts[80][33];
    const int b = blockIdx.y, t0 = blockIdx.x * 32, tid = threadIdx.x;
    const int tl = tid & 31, cw = tid >> 5;
    for (int c = cw; c < 80; c += 8)
        ts[c][tl] = mels[((size_t)b * 80 + c) * 1024 + t0 + tl];
    __syncthreads();
    const int c0 = (tid & 31) * 4, tw = tid >> 5;
    for (int tt = tw; tt < 32; tt += 8) {
        #pragma unroll
        for (int j = 0; j < 4; j++) {
            const int c = c0 + j;
            const float x = (c < 80) ? ts[c][tt] : 0.f;
            const __half h = __float2half_rn(x);
            const size_t o = ((size_t)b * 1024 + t0 + tt) * 128 + c;
            g_M1h[o] = h;
            g_M1l[o] = __float2half_rn(x - __half2float(h));
        }
    }
}

// ============================================================
// conv6 (1x1, 768->64) + bias + transpose. X is [b][t][768] fp32.
// ============================================================
__global__ __launch_bounds__(256) void conv6_kernel(
    const float* __restrict__ X, const float* __restrict__ W6,
    const float* __restrict__ b6, float* __restrict__ Z)
{
    __shared__ float Xs[64][65];
    __shared__ float Ws[64][65];
    const int tid = threadIdx.x;
    const int b   = blockIdx.y;
    const int t0  = blockIdx.x * 64;
    const int tdx = tid & 15;
    const int ttx = tid >> 4;

    float acc[4][4];
    #pragma unroll
    for (int i = 0; i < 4; i++)
        #pragma unroll
        for (int j = 0; j < 4; j++) acc[i][j] = 0.f;

    const int lt = tid & 63;
    const int lr = tid >> 6;

    for (int c0 = 0; c0 < CCH; c0 += 64) {
        #pragma unroll
        for (int r = 0; r < 16; r++) {
            const int trow = t0 + lr + 4 * r;
            Xs[lt][lr + 4 * r] = (trow < TP)
                ? X[((size_t)b * TP + trow) * CCH + c0 + lt] : 0.f;
            const int d = lr + r * 4;
            Ws[d][lt] = W6[(size_t)d * CCH + c0 + lt];
        }
        __syncthreads();
        #pragma unroll 8
        for (int ci = 0; ci < 64; ci++) {
            float wv[4], x[4];
            #pragma unroll
            for (int i = 0; i < 4; i++) wv[i] = Ws[tdx * 4 + i][ci];
            #pragma unroll
            for (int j = 0; j < 4; j++) x[j] = Xs[ci][ttx * 4 + j];
            #pragma unroll
            for (int i = 0; i < 4; i++)
                #pragma unroll
                for (int j = 0; j < 4; j++)
                    acc[i][j] = fmaf(wv[i], x[j], acc[i][j]);
        }
        __syncthreads();
    }
    #pragma unroll
    for (int i = 0; i < 4; i++) {
        const int d = tdx * 4 + i;
        const float bias = b6[d];
        #pragma unroll
        for (int j = 0; j < 4; j++) {
            const int t = t0 + ttx * 4 + j;
            if (t < TP)
                Z[((size_t)(b * TP + t)) * DDIM + d] = acc[i][j] + bias;
        }
    }
}

// ============================================================
// VQ prep / VQ / finalize (unchanged, validated in round 1)
// ============================================================
__global__ void prep_vq(const float* __restrict__ E)
{
    const int e = threadIdx.x;
    float s = 0.f;
    #pragma unroll
    for (int d = 0; d < DDIM; d++) {
        const float v = E[(size_t)e * DDIM + d];
        s = fmaf(v, v, s);
        g_Et[d * MEMB + e] = v;
    }
    g_esq[e] = s;
    g_counts[e] = 0;
}

__global__ __launch_bounds__(256) void vq_kernel(
    const float* __restrict__ Z, const float* __restrict__ E,
    float* __restrict__ out)
{
    __shared__ float zsh[8][64];
    __shared__ float pw[8];
    const int tid  = threadIdx.x;
    const int w    = tid >> 5;
    const int lane = tid & 31;
    const int vec  = blockIdx.x * 8 + w;

    zsh[w][lane]      = Z[(size_t)vec * 64 + lane];
    zsh[w][lane + 32] = Z[(size_t)vec * 64 + lane + 32];
    __syncwarp();

    float best = 3.4e38f;
    int   bidx = 0;
    #pragma unroll
    for (int i = 0; i < 16; i++) {
        const int e = lane + 32 * i;
        float dot = 0.f;
        #pragma unroll
        for (int d = 0; d < 64; d++)
            dot = fmaf(zsh[w][d], g_Et[d * MEMB + e], dot);
        const float dist = g_esq[e] - 2.f * dot;
        if (dist < best) { best = dist; bidx = e; }
    }
    #pragma unroll
    for (int off = 16; off > 0; off >>= 1) {
        const float ob = __shfl_down_sync(0xFFFFFFFFu, best, off);
        const int   oi = __shfl_down_sync(0xFFFFFFFFu, bidx, off);
        if (ob < best || (ob == best && oi < bidx)) { best = ob; bidx = oi; }
    }
    bidx = __shfl_sync(0xFFFFFFFFu, bidx, 0);

    float lsum = 0.f;
    #pragma unroll
    for (int h = 0; h < 2; h++) {
        const int d   = lane + 32 * h;
        const float zv = zsh[w][d];
        const float q  = E[(size_t)bidx * 64 + d];
        out[(size_t)vec * 64 + d] = zv + (q - zv);
        const float diff = zv - q;
        lsum = fmaf(diff, diff, lsum);
    }
    #pragma unroll
    for (int off = 16; off > 0; off >>= 1)
        lsum += __shfl_down_sync(0xFFFFFFFFu, lsum, off);

    if (lane == 0) {
        pw[w] = lsum;
        atomicAdd(&g_counts[bidx], 1);
    }
    __syncthreads();
    if (tid == 0) {
        float s = 0.f;
        #pragma unroll
        for (int i = 0; i < 8; i++) s += pw[i];
        g_partial[blockIdx.x] = s;
    }
}

__global__ __launch_bounds__(1024) void finalize_kernel(float* __restrict__ out)
{
    __shared__ float sh[1024];
    const int tid = threadIdx.x;
    float s = 0.f;
    for (int i = tid; i < NPART; i += 1024) s += g_partial[i];
    sh[tid] = s; __syncthreads();
    for (int off = 512; off > 0; off >>= 1) {
        if (tid < off) sh[tid] += sh[tid + off];
        __syncthreads();
    }
    const float total = sh[0];
    __syncthreads();
    float h = 0.f;
    if (tid < MEMB) {
        const float p = (float)g_counts[tid] / (float)NVEC;
        h = p * logf(p + 1e-10f);
    }
    sh[tid] = h; __syncthreads();
    for (int off = 512; off > 0; off >>= 1) {
        if (tid < off) sh[tid] += sh[tid + off];
        __syncthreads();
    }
    if (tid == 0) {
        out[(size_t)NVEC * DDIM]     = 0.25f * total / (float)((size_t)NVEC * DDIM);
        out[(size_t)NVEC * DDIM + 1] = expf(-sh[0]);
    }
}

// ============================================================
// launch
// ============================================================
extern "C" void kernel_launch(void* const* d_in, const int* in_sizes, int n_in,
                              void* d_out, int out_size)
{
    const float* mels  = (const float*)d_in[0];
    const float* w1    = (const float*)d_in[1];
    const float* w2    = (const float*)d_in[2];
    const float* w3    = (const float*)d_in[3];
    const float* w4    = (const float*)d_in[4];
    const float* w5    = (const float*)d_in[5];
    const float* w6    = (const float*)d_in[6];
    const float* b6    = (const float*)d_in[7];
    const float* gamma = (const float*)d_in[8];
    const float* beta  = (const float*)d_in[9];
    const float* mean  = (const float*)d_in[10];
    const float* var   = (const float*)d_in[11];
    const float* emb   = (const float*)d_in[12];
    float* out = (float*)d_out;

    __half *XAh, *XAl, *XBh, *XBl, *M1h, *M1l;
    __half *W1h, *W1l, *W2h, *W2l, *W3h, *W3l, *W4h, *W4l, *W5h, *W5l;
    float *C5, *zbuf;
    cudaGetSymbolAddress((void**)&XAh, g_XAh);
    cudaGetSymbolAddress((void**)&XAl, g_XAl);
    cudaGetSymbolAddress((void**)&XBh, g_XBh);
    cudaGetSymbolAddress((void**)&XBl, g_XBl);
    cudaGetSymbolAddress((void**)&M1h, g_M1h);
    cudaGetSymbolAddress((void**)&M1l, g_M1l);
    cudaGetSymbolAddress((void**)&C5,  g_C5);
    cudaGetSymbolAddress((void**)&zbuf, g_z);
    cudaGetSymbolAddress((void**)&W1h, g_W1h); cudaGetSymbolAddress((void**)&W1l, g_W1l);
    cudaGetSymbolAddress((void**)&W2h, g_W2h); cudaGetSymbolAddress((void**)&W2l, g_W2l);
    cudaGetSymbolAddress((void**)&W3h, g_W3h); cudaGetSymbolAddress((void**)&W3l, g_W3l);
    cudaGetSymbolAddress((void**)&W4h, g_W4h); cudaGetSymbolAddress((void**)&W4l, g_W4l);
    cudaGetSymbolAddress((void**)&W5h, g_W5h); cudaGetSymbolAddress((void**)&W5l, g_W5l);

    cudaFuncSetAttribute(conv_mma<3,1,0,true>,  cudaFuncAttributeMaxDynamicSharedMemorySize, SM_TOT);
    cudaFuncSetAttribute(conv_mma<3,1,1,true>,  cudaFuncAttributeMaxDynamicSharedMemorySize, SM_TOT);
    cudaFuncSetAttribute(conv_mma<4,2,1,true>,  cudaFuncAttributeMaxDynamicSharedMemorySize, SM_TOT);
    cudaFuncSetAttribute(conv_mma<3,1,1,false>, cudaFuncAttributeMaxDynamicSharedMemorySize, SM_TOT);

    // --- prep ---
    prep_w<<<(768*3*128 + 255)/256, 256>>>(w1, W1h, W1l, 80, 128, 3);
    prep_w<<<(768*3*768 + 255)/256, 256>>>(w2, W2h, W2l, 768, 768, 3);
    prep_w<<<(768*4*768 + 255)/256, 256>>>(w3, W3h, W3l, 768, 768, 4);
    prep_w<<<(768*3*768 + 255)/256, 256>>>(w4, W4h, W4l, 768, 768, 3);
    prep_w<<<(768*3*768 + 255)/256, 256>>>(w5, W5h, W5l, 768, 768, 3);
    prep_mels<<<dim3(32, BATCH), 256>>>(mels);

    // --- conv stack (mma.sync fp16 3-term split) ---
    conv_mma<3,1,0,true><<<dim3(8, 6, BATCH), 256, SM_TOT>>>(
        M1h, M1l, W1h, W1l, gamma, beta, mean, var,
        XAh, XAl, nullptr, 128, 1024, 1022);
    conv_mma<3,1,1,true><<<dim3(8, 6, BATCH), 256, SM_TOT>>>(
        XAh, XAl, W2h, W2l, gamma+CCH, beta+CCH, mean+CCH, var+CCH,
        XBh, XBl, nullptr, 768, 1022, 1022);
    conv_mma<4,2,1,true><<<dim3(4, 6, BATCH), 256, SM_TOT>>>(
        XBh, XBl, W3h, W3l, gamma+2*CCH, beta+2*CCH, mean+2*CCH, var+2*CCH,
        XAh, XAl, nullptr, 768, 1022, 511);
    conv_mma<3,1,1,true><<<dim3(4, 6, BATCH), 256, SM_TOT>>>(
        XAh, XAl, W4h, W4l, gamma+3*CCH, beta+3*CCH, mean+3*CCH, var+3*CCH,
        XBh, XBl, nullptr, 768, 511, 511);
    conv_mma<3,1,1,false><<<dim3(4, 6, BATCH), 256, SM_TOT>>>(
        XBh, XBl, W5h, W5l, gamma+4*CCH, beta+4*CCH, mean+4*CCH, var+4*CCH,
        nullptr, nullptr, C5, 768, 511, 511);

    // --- tail ---
    conv6_kernel<<<dim3(8, BATCH), 256>>>(C5, w6, b6, zbuf);
    prep_vq<<<1, MEMB>>>(emb);
    vq_kernel<<<NPART, 256>>>(zbuf, emb, out);
    finalize_kernel<<<1, 1024>>>(out);
}